// round 1
// baseline (speedup 1.0000x reference)
#include <cuda_runtime.h>
#include <cuda_bf16.h>

// GRU_66314295050287 on GB300 (sm_103a)
// Shapes: x (32,2048,32,12) f32; M = 65536 sequences, each [FE=32][T=12] contiguous.
// gates[m,t,g] = sum_f x[m,f,t] * w_ih[g,f] + b_ih[g]; scalar-hidden GRU over T=12;
// out[m,k] = sum_t relu(h_t) * lin_w[k,t] + lin_b[k].
//
// Strategy: HBM-bound (100.7 MB in). Block of 256 threads owns 256 consecutive
// sequences (contiguous 384 KB region). Loop over 4 f-chunks of 8: cooperatively
// stage 256 x 96 floats (96 KB + pad) into smem with fully coalesced float4
// loads, then thread-per-sequence accumulates 36 gate FMAs per f from smem
// (stride 100 floats == 4 mod 32 -> conflict-free 16B LDS phases).

#define T_DIM        12
#define FE_DIM       32
#define OUT_DIM      3
#define SEQ_PER_BLK  256
#define NTHREADS     256
#define CHUNK_F      8
#define NCHUNKS      (FE_DIM / CHUNK_F)          // 4
#define CHUNK_FLOATS (CHUNK_F * T_DIM)           // 96 floats per seq per chunk
#define CHUNK_VEC4   (CHUNK_FLOATS / 4)          // 24 float4
#define SSTRIDE      (CHUNK_FLOATS + 4)          // 100 floats: pad -> bank-conflict-free
#define SEQ_VEC4     96                          // 384 floats per sequence = 96 float4

__device__ __forceinline__ float fast_sigmoid(float x) {
    // 1/(1+e^-x): safe at both tails (exp->inf gives 0, exp->0 gives 1)
    return 1.0f / (1.0f + __expf(-x));
}
__device__ __forceinline__ float fast_tanh(float x) {
    // 1 - 2/(1+e^{2x}): safe at both tails (no inf-inf)
    float e = __expf(2.0f * x);
    return 1.0f - 2.0f / (1.0f + e);
}

extern __shared__ float smem[];

__global__ void __launch_bounds__(NTHREADS, 2)
gru_kernel(const float* __restrict__ x,
           const float* __restrict__ w_ih,   // [3][32]
           const float* __restrict__ w_hh,   // [3][1]
           const float* __restrict__ b_ih,   // [3]
           const float* __restrict__ b_hh,   // [3]
           const float* __restrict__ lin_w,  // [3][12]
           const float* __restrict__ lin_b,  // [3]
           float* __restrict__ out)          // [M][3]
{
    float* sdata = smem;                                  // SEQ_PER_BLK * SSTRIDE
    float* s_wih = smem + SEQ_PER_BLK * SSTRIDE;          // 96
    float* s_lw  = s_wih + 96;                            // 36

    const int tid = threadIdx.x;
    if (tid < 96) s_wih[tid] = w_ih[tid];
    if (tid < 36) s_lw[tid]  = lin_w[tid];

    const int m0 = blockIdx.x * SEQ_PER_BLK;

    // Gate accumulators, bias folded into init.
    const float bi0 = b_ih[0], bi1 = b_ih[1], bi2 = b_ih[2];
    float gx0[T_DIM], gx1[T_DIM], gx2[T_DIM];
#pragma unroll
    for (int t = 0; t < T_DIM; ++t) { gx0[t] = bi0; gx1[t] = bi1; gx2[t] = bi2; }

    const float4* __restrict__ x4 = reinterpret_cast<const float4*>(x);

    for (int c = 0; c < NCHUNKS; ++c) {
        __syncthreads();  // previous chunk's smem reads done (also orders weight stores)

        // Cooperative coalesced load: 256 seq * 24 float4 = 6144 float4.
        // Each sequence's chunk is a contiguous, 128B-aligned 384B segment.
#pragma unroll
        for (int k = 0; k < (SEQ_PER_BLK * CHUNK_VEC4) / NTHREADS; ++k) {
            int i  = k * NTHREADS + tid;
            int ms = i / CHUNK_VEC4;
            int q  = i - ms * CHUNK_VEC4;
            float4 v = x4[(long)(m0 + ms) * SEQ_VEC4 + c * CHUNK_VEC4 + q];
            reinterpret_cast<float4*>(sdata + ms * SSTRIDE)[q] = v;
        }
        __syncthreads();

        // Thread-per-sequence gate accumulation from smem.
        const float* my = sdata + tid * SSTRIDE;
#pragma unroll
        for (int fl = 0; fl < CHUNK_F; ++fl) {
            int f = c * CHUNK_F + fl;
            float w0 = s_wih[f];
            float w1 = s_wih[32 + f];
            float w2 = s_wih[64 + f];
            float4 a = reinterpret_cast<const float4*>(my + fl * T_DIM)[0];
            float4 b = reinterpret_cast<const float4*>(my + fl * T_DIM)[1];
            float4 d = reinterpret_cast<const float4*>(my + fl * T_DIM)[2];
            float xt[T_DIM] = {a.x, a.y, a.z, a.w, b.x, b.y, b.z, b.w, d.x, d.y, d.z, d.w};
#pragma unroll
            for (int t = 0; t < T_DIM; ++t) {
                gx0[t] = fmaf(xt[t], w0, gx0[t]);
                gx1[t] = fmaf(xt[t], w1, gx1[t]);
                gx2[t] = fmaf(xt[t], w2, gx2[t]);
            }
        }
    }

    // Scalar-hidden GRU recurrence + fused relu + linear head.
    const float wh0 = w_hh[0], wh1 = w_hh[1], wh2 = w_hh[2];
    const float bh0 = b_hh[0], bh1 = b_hh[1], bh2 = b_hh[2];
    float o0 = lin_b[0], o1 = lin_b[1], o2 = lin_b[2];
    float h = 0.0f;
#pragma unroll
    for (int t = 0; t < T_DIM; ++t) {
        float r = fast_sigmoid(gx0[t] + wh0 * h + bh0);
        float z = fast_sigmoid(gx1[t] + wh1 * h + bh1);
        float n = fast_tanh(gx2[t] + r * (wh2 * h + bh2));
        h = (1.0f - z) * n + z * h;
        float hr = fmaxf(h, 0.0f);
        o0 = fmaf(hr, s_lw[t],       o0);
        o1 = fmaf(hr, s_lw[12 + t],  o1);
        o2 = fmaf(hr, s_lw[24 + t],  o2);
    }

    const long m = m0 + tid;
    out[m * 3 + 0] = o0;
    out[m * 3 + 1] = o1;
    out[m * 3 + 2] = o2;
}

extern "C" void kernel_launch(void* const* d_in, const int* in_sizes, int n_in,
                              void* d_out, int out_size) {
    const float* x     = (const float*)d_in[0];
    const float* w_ih  = (const float*)d_in[1];
    const float* w_hh  = (const float*)d_in[2];
    const float* b_ih  = (const float*)d_in[3];
    const float* b_hh  = (const float*)d_in[4];
    const float* lin_w = (const float*)d_in[5];
    const float* lin_b = (const float*)d_in[6];
    float* out = (float*)d_out;

    const int M = in_sizes[0] / (FE_DIM * T_DIM);   // 65536
    const int grid = M / SEQ_PER_BLK;               // 256

    const size_t smem_bytes = (size_t)(SEQ_PER_BLK * SSTRIDE + 96 + 36) * sizeof(float);
    cudaFuncSetAttribute(gru_kernel, cudaFuncAttributeMaxDynamicSharedMemorySize,
                         (int)smem_bytes);

    gru_kernel<<<grid, NTHREADS, smem_bytes>>>(x, w_ih, w_hh, b_ih, b_hh,
                                               lin_w, lin_b, out);
}

// round 3
// speedup vs baseline: 1.5185x; 1.5185x over previous
#include <cuda_runtime.h>
#include <cuda_bf16.h>
#include <cstdint>

// GRU_66314295050287 on GB300 (sm_103a) — R3: cp.async double-buffered pipeline
// (R2 + missing <cstdint> fix).
// x (32,2048,32,12) f32; M = 65536 sequences, each [FE=32][T=12] contiguous (1536 B).
// gates[m,t,g] = sum_f x[m,f,t]*w_ih[g,f] + b_ih[g]; scalar-hidden GRU over T=12;
// out[m,k] = relu(h_t) @ lin_w^T + lin_b.
//
// Block = 256 threads = 256 sequences. 8 chunks of F=4 (48 floats = 12 float4 per
// seq). Chunk c+1 is fetched via cp.async into the alternate smem buffer while
// chunk c is consumed -> load/compute overlap instead of serialization.

#define T_DIM        12
#define FE_DIM       32
#define SEQ_PER_BLK  256
#define NTHREADS     256
#define CHUNK_F      4
#define NCHUNKS      (FE_DIM / CHUNK_F)          // 8
#define CHUNK_FLOATS (CHUNK_F * T_DIM)           // 48
#define CHUNK_VEC4   (CHUNK_FLOATS / 4)          // 12 float4 per seq per chunk
#define SSTRIDE      (CHUNK_FLOATS + 4)          // 52 floats; 52%32=20 -> conflict-free phases
#define BUF_FLOATS   (SEQ_PER_BLK * SSTRIDE)     // 13312 floats per buffer
#define SEQ_VEC4     96                          // 1536 B per sequence

__device__ __forceinline__ float fast_sigmoid(float x) {
    return 1.0f / (1.0f + __expf(-x));
}
__device__ __forceinline__ float fast_tanh(float x) {
    float e = __expf(2.0f * x);
    return 1.0f - 2.0f / (1.0f + e);
}

__device__ __forceinline__ void cp_async16(unsigned int saddr, const void* gptr) {
    asm volatile("cp.async.cg.shared.global [%0], [%1], 16;\n" :: "r"(saddr), "l"(gptr));
}
__device__ __forceinline__ void cp_commit() {
    asm volatile("cp.async.commit_group;\n");
}
template <int N>
__device__ __forceinline__ void cp_wait() {
    asm volatile("cp.async.wait_group %0;\n" :: "n"(N));
}

extern __shared__ float smem[];

__global__ void __launch_bounds__(NTHREADS, 2)
gru_kernel(const float* __restrict__ x,
           const float* __restrict__ w_ih,   // [3][32]
           const float* __restrict__ w_hh,   // [3][1]
           const float* __restrict__ b_ih,   // [3]
           const float* __restrict__ b_hh,   // [3]
           const float* __restrict__ lin_w,  // [3][12]
           const float* __restrict__ lin_b,  // [3]
           float* __restrict__ out)          // [M][3]
{
    float* buf0  = smem;                       // 2 x BUF_FLOATS
    float* s_wih = smem + 2 * BUF_FLOATS;      // 96
    float* s_lw  = s_wih + 96;                 // 36

    const int tid = threadIdx.x;
    if (tid < 96) s_wih[tid] = w_ih[tid];
    if (tid < 36) s_lw[tid]  = lin_w[tid];

    const int m0 = blockIdx.x * SEQ_PER_BLK;
    const float4* __restrict__ x4 = reinterpret_cast<const float4*>(x);

    const unsigned int sbase = (unsigned int)__cvta_generic_to_shared(buf0);

    // Issue loads for one chunk into buffer b. 256 seq * 12 float4 -> 12 per thread.
    auto issue_chunk = [&](int c, int b) {
#pragma unroll
        for (int k = 0; k < (SEQ_PER_BLK * CHUNK_VEC4) / NTHREADS; ++k) {
            int i  = k * NTHREADS + tid;
            int ms = i / CHUNK_VEC4;
            int q  = i - ms * CHUNK_VEC4;
            const void* g = (const void*)(x4 + (long)(m0 + ms) * SEQ_VEC4 + c * CHUNK_VEC4 + q);
            unsigned int s = sbase + (unsigned int)((b * BUF_FLOATS + ms * SSTRIDE + q * 4) * 4);
            cp_async16(s, g);
        }
        cp_commit();
    };

    const float bi0 = b_ih[0], bi1 = b_ih[1], bi2 = b_ih[2];
    float gx0[T_DIM], gx1[T_DIM], gx2[T_DIM];
#pragma unroll
    for (int t = 0; t < T_DIM; ++t) { gx0[t] = bi0; gx1[t] = bi1; gx2[t] = bi2; }

    issue_chunk(0, 0);

#pragma unroll
    for (int c = 0; c < NCHUNKS; ++c) {
        if (c + 1 < NCHUNKS) {
            issue_chunk(c + 1, (c + 1) & 1);
            cp_wait<1>();           // chunk c landed
        } else {
            cp_wait<0>();
        }
        __syncthreads();            // all threads see chunk c (and weights on c==0)

        const float* my = buf0 + (c & 1) * BUF_FLOATS + tid * SSTRIDE;
#pragma unroll
        for (int fl = 0; fl < CHUNK_F; ++fl) {
            int f = c * CHUNK_F + fl;
            float w0 = s_wih[f];
            float w1 = s_wih[32 + f];
            float w2 = s_wih[64 + f];
            float4 a = reinterpret_cast<const float4*>(my + fl * T_DIM)[0];
            float4 b = reinterpret_cast<const float4*>(my + fl * T_DIM)[1];
            float4 d = reinterpret_cast<const float4*>(my + fl * T_DIM)[2];
            float xt[T_DIM] = {a.x, a.y, a.z, a.w, b.x, b.y, b.z, b.w, d.x, d.y, d.z, d.w};
#pragma unroll
            for (int t = 0; t < T_DIM; ++t) {
                gx0[t] = fmaf(xt[t], w0, gx0[t]);
                gx1[t] = fmaf(xt[t], w1, gx1[t]);
                gx2[t] = fmaf(xt[t], w2, gx2[t]);
            }
        }
        __syncthreads();            // chunk c consumed; its buffer may be re-filled
    }

    // Scalar-hidden GRU recurrence + relu + linear head.
    const float wh0 = w_hh[0], wh1 = w_hh[1], wh2 = w_hh[2];
    const float bh0 = b_hh[0], bh1 = b_hh[1], bh2 = b_hh[2];
    float o0 = lin_b[0], o1 = lin_b[1], o2 = lin_b[2];
    float h = 0.0f;
#pragma unroll
    for (int t = 0; t < T_DIM; ++t) {
        float r = fast_sigmoid(gx0[t] + wh0 * h + bh0);
        float z = fast_sigmoid(gx1[t] + wh1 * h + bh1);
        float n = fast_tanh(gx2[t] + r * (wh2 * h + bh2));
        h = (1.0f - z) * n + z * h;
        float hr = fmaxf(h, 0.0f);
        o0 = fmaf(hr, s_lw[t],       o0);
        o1 = fmaf(hr, s_lw[12 + t],  o1);
        o2 = fmaf(hr, s_lw[24 + t],  o2);
    }

    // Coalesced epilogue: stage [256][3] floats in smem, write 192 float4.
    float* s_out = buf0;            // reuse buffer 0 (all compute done)
    s_out[tid * 3 + 0] = o0;        // stride 3 (coprime with 32) -> conflict-free
    s_out[tid * 3 + 1] = o1;
    s_out[tid * 3 + 2] = o2;
    __syncthreads();
    if (tid < (SEQ_PER_BLK * 3) / 4) {
        reinterpret_cast<float4*>(out + (long)m0 * 3)[tid] =
            reinterpret_cast<const float4*>(s_out)[tid];
    }
}

extern "C" void kernel_launch(void* const* d_in, const int* in_sizes, int n_in,
                              void* d_out, int out_size) {
    const float* x     = (const float*)d_in[0];
    const float* w_ih  = (const float*)d_in[1];
    const float* w_hh  = (const float*)d_in[2];
    const float* b_ih  = (const float*)d_in[3];
    const float* b_hh  = (const float*)d_in[4];
    const float* lin_w = (const float*)d_in[5];
    const float* lin_b = (const float*)d_in[6];
    float* out = (float*)d_out;

    const int M = in_sizes[0] / (FE_DIM * T_DIM);   // 65536
    const int grid = M / SEQ_PER_BLK;               // 256

    const size_t smem_bytes = (size_t)(2 * BUF_FLOATS + 96 + 36) * sizeof(float);
    cudaFuncSetAttribute(gru_kernel, cudaFuncAttributeMaxDynamicSharedMemorySize,
                         (int)smem_bytes);

    gru_kernel<<<grid, NTHREADS, smem_bytes>>>(x, w_ih, w_hh, b_ih, b_hh,
                                               lin_w, lin_b, out);
}

// round 6
// speedup vs baseline: 1.6427x; 1.0818x over previous
#include <cuda_runtime.h>
#include <cuda_bf16.h>
#include <cstdint>

// GRU_66314295050287 on GB300 (sm_103a) — R4: fine-grained grid for load balance.
// R3 (cp.async double-buffered pipeline) but 1024 blocks x 64 threads:
// 1024 = 6*148 + 136 -> 7 vs 6.92 blocks/SM = 1.2% imbalance (was ~16% at 256 blocks),
// and 8 co-resident block pipelines per SM deepen effective MLP.

#define T_DIM        12
#define FE_DIM       32
#define SEQ_PER_BLK  64
#define NTHREADS     64
#define CHUNK_F      4
#define NCHUNKS      (FE_DIM / CHUNK_F)          // 8
#define CHUNK_FLOATS (CHUNK_F * T_DIM)           // 48
#define CHUNK_VEC4   (CHUNK_FLOATS / 4)          // 12 float4 per seq per chunk
#define SSTRIDE      (CHUNK_FLOATS + 4)          // 52 floats; conflict-free LDS.128 phases
#define BUF_FLOATS   (SEQ_PER_BLK * SSTRIDE)     // 3328 floats per buffer
#define SEQ_VEC4     96                          // 1536 B per sequence

__device__ __forceinline__ float fast_sigmoid(float x) {
    return 1.0f / (1.0f + __expf(-x));
}
__device__ __forceinline__ float fast_tanh(float x) {
    float e = __expf(2.0f * x);
    return 1.0f - 2.0f / (1.0f + e);
}

__device__ __forceinline__ void cp_async16(unsigned int saddr, const void* gptr) {
    asm volatile("cp.async.cg.shared.global [%0], [%1], 16;\n" :: "r"(saddr), "l"(gptr));
}
__device__ __forceinline__ void cp_commit() {
    asm volatile("cp.async.commit_group;\n");
}
template <int N>
__device__ __forceinline__ void cp_wait() {
    asm volatile("cp.async.wait_group %0;\n" :: "n"(N));
}

extern __shared__ float smem[];

__global__ void __launch_bounds__(NTHREADS, 8)
gru_kernel(const float* __restrict__ x,
           const float* __restrict__ w_ih,   // [3][32]
           const float* __restrict__ w_hh,   // [3][1]
           const float* __restrict__ b_ih,   // [3]
           const float* __restrict__ b_hh,   // [3]
           const float* __restrict__ lin_w,  // [3][12]
           const float* __restrict__ lin_b,  // [3]
           float* __restrict__ out)          // [M][3]
{
    float* buf0  = smem;                       // 2 x BUF_FLOATS
    float* s_wih = smem + 2 * BUF_FLOATS;      // 96
    float* s_lw  = s_wih + 96;                 // 36

    const int tid = threadIdx.x;
#pragma unroll
    for (int i = tid; i < 96; i += NTHREADS) s_wih[i] = w_ih[i];
    if (tid < 36) s_lw[tid] = lin_w[tid];

    const int m0 = blockIdx.x * SEQ_PER_BLK;
    const float4* __restrict__ x4 = reinterpret_cast<const float4*>(x);

    const unsigned int sbase = (unsigned int)__cvta_generic_to_shared(buf0);

    // Issue loads for one chunk into buffer b. 64 seq * 12 float4 -> 12 per thread.
    auto issue_chunk = [&](int c, int b) {
#pragma unroll
        for (int k = 0; k < (SEQ_PER_BLK * CHUNK_VEC4) / NTHREADS; ++k) {
            int i  = k * NTHREADS + tid;
            int ms = i / CHUNK_VEC4;
            int q  = i - ms * CHUNK_VEC4;
            const void* g = (const void*)(x4 + (long)(m0 + ms) * SEQ_VEC4 + c * CHUNK_VEC4 + q);
            unsigned int s = sbase + (unsigned int)((b * BUF_FLOATS + ms * SSTRIDE + q * 4) * 4);
            cp_async16(s, g);
        }
        cp_commit();
    };

    const float bi0 = b_ih[0], bi1 = b_ih[1], bi2 = b_ih[2];
    float gx0[T_DIM], gx1[T_DIM], gx2[T_DIM];
#pragma unroll
    for (int t = 0; t < T_DIM; ++t) { gx0[t] = bi0; gx1[t] = bi1; gx2[t] = bi2; }

    issue_chunk(0, 0);

#pragma unroll
    for (int c = 0; c < NCHUNKS; ++c) {
        if (c + 1 < NCHUNKS) {
            issue_chunk(c + 1, (c + 1) & 1);
            cp_wait<1>();           // chunk c landed
        } else {
            cp_wait<0>();
        }
        __syncthreads();            // all threads see chunk c (and weights on c==0)

        const float* my = buf0 + (c & 1) * BUF_FLOATS + tid * SSTRIDE;
#pragma unroll
        for (int fl = 0; fl < CHUNK_F; ++fl) {
            int f = c * CHUNK_F + fl;
            float w0 = s_wih[f];
            float w1 = s_wih[32 + f];
            float w2 = s_wih[64 + f];
            float4 a = reinterpret_cast<const float4*>(my + fl * T_DIM)[0];
            float4 b = reinterpret_cast<const float4*>(my + fl * T_DIM)[1];
            float4 d = reinterpret_cast<const float4*>(my + fl * T_DIM)[2];
            float xt[T_DIM] = {a.x, a.y, a.z, a.w, b.x, b.y, b.z, b.w, d.x, d.y, d.z, d.w};
#pragma unroll
            for (int t = 0; t < T_DIM; ++t) {
                gx0[t] = fmaf(xt[t], w0, gx0[t]);
                gx1[t] = fmaf(xt[t], w1, gx1[t]);
                gx2[t] = fmaf(xt[t], w2, gx2[t]);
            }
        }
        __syncthreads();            // chunk c consumed; its buffer may be re-filled
    }

    // Scalar-hidden GRU recurrence + relu + linear head.
    const float wh0 = w_hh[0], wh1 = w_hh[1], wh2 = w_hh[2];
    const float bh0 = b_hh[0], bh1 = b_hh[1], bh2 = b_hh[2];
    float o0 = lin_b[0], o1 = lin_b[1], o2 = lin_b[2];
    float h = 0.0f;
#pragma unroll
    for (int t = 0; t < T_DIM; ++t) {
        float r = fast_sigmoid(gx0[t] + wh0 * h + bh0);
        float z = fast_sigmoid(gx1[t] + wh1 * h + bh1);
        float n = fast_tanh(gx2[t] + r * (wh2 * h + bh2));
        h = (1.0f - z) * n + z * h;
        float hr = fmaxf(h, 0.0f);
        o0 = fmaf(hr, s_lw[t],       o0);
        o1 = fmaf(hr, s_lw[12 + t],  o1);
        o2 = fmaf(hr, s_lw[24 + t],  o2);
    }

    // Coalesced epilogue: stage [64][3] floats in smem, write 48 float4.
    float* s_out = buf0;            // reuse buffer 0 (all compute done)
    s_out[tid * 3 + 0] = o0;        // stride 3 coprime with 32 -> conflict-free
    s_out[tid * 3 + 1] = o1;
    s_out[tid * 3 + 2] = o2;
    __syncthreads();
    if (tid < (SEQ_PER_BLK * 3) / 4) {
        reinterpret_cast<float4*>(out + (long)m0 * 3)[tid] =
            reinterpret_cast<const float4*>(s_out)[tid];
    }
}

extern "C" void kernel_launch(void* const* d_in, const int* in_sizes, int n_in,
                              void* d_out, int out_size) {
    const float* x     = (const float*)d_in[0];
    const float* w_ih  = (const float*)d_in[1];
    const float* w_hh  = (const float*)d_in[2];
    const float* b_ih  = (const float*)d_in[3];
    const float* b_hh  = (const float*)d_in[4];
    const float* lin_w = (const float*)d_in[5];
    const float* lin_b = (const float*)d_in[6];
    float* out = (float*)d_out;

    const int M = in_sizes[0] / (FE_DIM * T_DIM);   // 65536
    const int grid = M / SEQ_PER_BLK;               // 1024

    const size_t smem_bytes = (size_t)(2 * BUF_FLOATS + 96 + 36) * sizeof(float);
    cudaFuncSetAttribute(gru_kernel, cudaFuncAttributeMaxDynamicSharedMemorySize,
                         (int)smem_bytes);

    gru_kernel<<<grid, NTHREADS, smem_bytes>>>(x, w_ih, w_hh, b_ih, b_hh,
                                               lin_w, lin_b, out);
}